// round 4
// baseline (speedup 1.0000x reference)
#include <cuda_runtime.h>
#include <math.h>

#define B_ 8
#define N_ 4096
#define K_ 16
#define D_ 256
#define M_ (B_*N_)          // 32768 query rows

__device__ int   g_idx[M_*K_];        // 2 MB
__device__ float g_agg[M_*D_];        // 33.5 MB

typedef unsigned long long ull;

// packed f32x2 FMA: d = a*b + c  (two fp32 lanes per instruction)
__device__ __forceinline__ ull fma2(ull a, ull b, ull c) {
    ull d;
    asm("fma.rn.f32x2 %0, %1, %2, %3;" : "=l"(d) : "l"(a), "l"(b), "l"(c));
    return d;
}
__device__ __forceinline__ ull pack2(float x) {
    ull d;
    asm("mov.b64 %0, {%1, %1};" : "=l"(d) : "f"(x));
    return d;
}

// ---------------------------------------------------------------------------
// Kernel 1: brute-force kNN, 4-way split scan: 4 threads per query (1024
// candidates each), sorted top-16 per split, 4-way merge. 256 thr = 64 queries.
// ---------------------------------------------------------------------------
__global__ __launch_bounds__(256) void knn_kernel(const float* __restrict__ coords)
{
    __shared__ float4 tile[256];
    __shared__ float  sd[256 * K_];
    __shared__ int    si[256 * K_];

    const int t = threadIdx.x;
    const int b  = blockIdx.x >> 6;                 // 64 blocks per batch
    const int q0 = (blockIdx.x & 63) << 6;          // 64 queries per block
    const int q  = q0 + (t & 63);
    const int split = t >> 6;                       // 0..3
    const float* cb = coords + (size_t)b * N_ * 3;

    float qx = cb[q*3+0], qy = cb[q*3+1], qz = cb[q*3+2];
    float qsq = qx*qx + qy*qy + qz*qz;

    float best[K_]; int bidx[K_];
#pragma unroll
    for (int s = 0; s < K_; s++) { best[s] = 3.4e38f; bidx[s] = 0; }

    const int base = split * 1024;
    for (int c0 = 0; c0 < 1024; c0 += 64) {
        __syncthreads();
        {   // cooperative: thread t loads chunk element for region t>>6
            int m = (t >> 6) * 1024 + c0 + (t & 63);
            float x = cb[m*3+0], y = cb[m*3+1], z = cb[m*3+2];
            tile[t] = make_float4(x, y, z, x*x + y*y + z*z);
        }
        __syncthreads();
        const float4* tl = tile + split * 64;
#pragma unroll 4
        for (int mm = 0; mm < 64; mm++) {
            float4 c = tl[mm];
            float d2 = qsq + c.w - 2.0f*(qx*c.x + qy*c.y + qz*c.z);
            if (d2 < best[K_-1]) {
                float d = d2; int id = base + c0 + mm;
#pragma unroll
                for (int s = 0; s < K_; s++) {
                    if (d < best[s]) {
                        float td = best[s]; int ti = bidx[s];
                        best[s] = d; bidx[s] = id;
                        d = td; id = ti;
                    }
                }
            }
        }
    }

#pragma unroll
    for (int s = 0; s < K_; s++) { sd[t*K_ + s] = best[s]; si[t*K_ + s] = bidx[s]; }
    __syncthreads();

    // 4-way merge by threads t < 64 (lexicographic (d2, idx) min)
    if (t < 64) {
        int ia[4] = {0,0,0,0};
        int* o = g_idx + (size_t)(b*N_ + q0 + t) * K_;
#pragma unroll
        for (int s = 0; s < K_; s++) {
            float bv = 3.5e38f; int bi = 0x7fffffff; int bl = 0;
#pragma unroll
            for (int l = 0; l < 4; l++) {
                int p = ia[l];
                float v  = (p < K_) ? sd[(t + l*64)*K_ + p] : 3.5e38f;
                int   ix = (p < K_) ? si[(t + l*64)*K_ + p] : 0x7fffffff;
                if (v < bv || (v == bv && ix < bi)) { bv = v; bi = ix; bl = l; }
            }
            o[s] = bi;
            ia[bl]++;
        }
    }
}

// ---------------------------------------------------------------------------
// Warp-per-row LayerNorm over smem rows. NW warps in the block.
// ---------------------------------------------------------------------------
template<int W, bool RELU, int NW>
__device__ __forceinline__ void ln_rows(float* buf, int rows,
                                        const float* __restrict__ g,
                                        const float* __restrict__ be)
{
    const int wid = threadIdx.x >> 5, lane = threadIdx.x & 31;
    constexpr int C = W / 32;
    for (int r = wid; r < rows; r += NW) {
        float* h = buf + r * W;
        float v[C]; float s = 0.f;
#pragma unroll
        for (int i = 0; i < C; i++) { v[i] = h[lane + i*32]; s += v[i]; }
#pragma unroll
        for (int o = 16; o; o >>= 1) s += __shfl_xor_sync(0xffffffffu, s, o);
        float mean = s * (1.0f / W);
        float s2 = 0.f;
#pragma unroll
        for (int i = 0; i < C; i++) { float d = v[i] - mean; s2 += d*d; }
#pragma unroll
        for (int o = 16; o; o >>= 1) s2 += __shfl_xor_sync(0xffffffffu, s2, o);
        float rstd = rsqrtf(s2 * (1.0f / W) + 1e-5f);
#pragma unroll
        for (int i = 0; i < C; i++) {
            int c = lane + i*32;
            float o2 = (v[i] - mean) * rstd * g[c] + be[c];
            if (RELU) o2 = fmaxf(o2, 0.f);
            h[c] = o2;
        }
    }
}

// ---------------------------------------------------------------------------
// Kernel 2: fused geom features + encoder MLP (10->64->128->256) + mean over K
// One block = 4 queries = 64 rows, 512 threads.
// smem: sW3 128KB | bufA 32KB | bufB 64KB = 224KB
// GEMMs use packed fma.rn.f32x2 (FFMA2): weight pairs come packed for free
// from LDS.128/LDG.128; activations broadcast-packed once per (row,k).
// ---------------------------------------------------------------------------
#define ENC_G 4
#define ENC_R 64
#define ENC_SMEM_FLOATS (32768 + 8192 + 16384)

__global__ __launch_bounds__(512, 1) void encoder_kernel(
    const float* __restrict__ coords,
    const float* __restrict__ W1, const float* __restrict__ b1,
    const float* __restrict__ g1, const float* __restrict__ be1,
    const float* __restrict__ W2, const float* __restrict__ b2,
    const float* __restrict__ g2, const float* __restrict__ be2,
    const float* __restrict__ W3, const float* __restrict__ b3,
    const float* __restrict__ g3, const float* __restrict__ be3)
{
    extern __shared__ float sm[];
    float* sW3  = sm;                 // 128*256
    float* bufA = sm + 32768;         // 64x128 (geom first, then h2)
    float* bufB = sm + 40960;         // 64x256 (h1 first, then h3)
    const int t = threadIdx.x;
    const int q0 = blockIdx.x * ENC_G;

    {   // stage W3 into smem
        float4* dst = (float4*)sW3; const float4* src = (const float4*)W3;
        for (int i = t; i < 32768/4; i += 512) dst[i] = src[i];
    }

    if (t < ENC_R) {    // geometric features, one thread per neighbor row
        int q  = q0 + (t >> 4);
        int kk = t & 15;
        int b  = q >> 12;
        int n  = q & (N_ - 1);
        const float* cb = coords + (size_t)b * N_ * 3;
        float qx = cb[n*3+0], qy = cb[n*3+1], qz = cb[n*3+2];
        int nb = g_idx[(size_t)q * K_ + kk];
        float rx = cb[nb*3+0] - qx, ry = cb[nb*3+1] - qy, rz = cb[nb*3+2] - qz;
        float dist = sqrtf(rx*rx + ry*ry + rz*rz);
        float inv  = 1.0f / (dist + 1e-6f);
        float nx = rx*inv, ny = ry*inv, nz = rz*inv;
        float* gm = bufA + t * 10;
        gm[0] = dist; gm[1] = rx; gm[2] = ry; gm[3] = rz;
        gm[4] = atan2f(ny, nx); gm[5] = atan2f(nz, nx); gm[6] = atan2f(nz, ny);
        gm[7] = nx; gm[8] = ny; gm[9] = nz;
    }
    __syncthreads();

    // ---- stage 1: geom[64][10] @ W1[10][64] -> bufB (stride 64), scalar ----
    {
        int j = t & 63, r0 = (t >> 6) * 8;
        float acc[8];
        float bj = b1[j];
#pragma unroll
        for (int r = 0; r < 8; r++) acc[r] = bj;
#pragma unroll
        for (int k = 0; k < 10; k++) {
            float w = W1[k*64 + j];
#pragma unroll
            for (int r = 0; r < 8; r++)
                acc[r] = fmaf(w, bufA[(r0 + r)*10 + k], acc[r]);
        }
#pragma unroll
        for (int r = 0; r < 8; r++) bufB[(r0 + r)*64 + j] = acc[r];
    }
    __syncthreads();
    ln_rows<64, true, 16>(bufB, ENC_R, g1, be1);
    __syncthreads();

    // ---- stage 2: h1[64][64] @ W2[64][128] -> bufA, 4r x 4c FFMA2 tile ----
    {
        const int j0 = (t & 31) * 4;       // 32 col groups of 4
        const int r0 = (t >> 5) * 4;       // 16 row groups of 4 => 64 rows
        ull acc[4][2];
        {
            const ull* bp = (const ull*)&b2[j0];
            ull bA = bp[0], bB = bp[1];
#pragma unroll
            for (int r = 0; r < 4; r++) { acc[r][0] = bA; acc[r][1] = bB; }
        }
        for (int k0 = 0; k0 < 64; k0 += 4) {
            float4 a[4];
#pragma unroll
            for (int r = 0; r < 4; r++) a[r] = *(const float4*)&bufB[(r0 + r)*64 + k0];
#pragma unroll
            for (int kk = 0; kk < 4; kk++) {
                const ull* wp = (const ull*)&W2[(k0+kk)*128 + j0];
                ull w0 = wp[0], w1 = wp[1];
#pragma unroll
                for (int r = 0; r < 4; r++) {
                    float av = (kk==0)?a[r].x:(kk==1)?a[r].y:(kk==2)?a[r].z:a[r].w;
                    ull ap = pack2(av);
                    acc[r][0] = fma2(ap, w0, acc[r][0]);
                    acc[r][1] = fma2(ap, w1, acc[r][1]);
                }
            }
        }
#pragma unroll
        for (int r = 0; r < 4; r++) {
            ull* dst = (ull*)&bufA[(r0 + r)*128 + j0];
            dst[0] = acc[r][0]; dst[1] = acc[r][1];
        }
    }
    __syncthreads();
    ln_rows<128, true, 16>(bufA, ENC_R, g2, be2);
    __syncthreads();

    // ---- stage 3: h2[64][128] @ W3[128][256] -> bufB, 4r x 8c FFMA2 tile ----
    {
        const int j0 = (t & 31) * 8;       // 32 col groups of 8
        const int r0 = (t >> 5) * 4;       // 16 row groups of 4
        ull acc[4][4];
        {
            const ull* bp = (const ull*)&b3[j0];
#pragma unroll
            for (int r = 0; r < 4; r++) {
                acc[r][0] = bp[0]; acc[r][1] = bp[1];
                acc[r][2] = bp[2]; acc[r][3] = bp[3];
            }
        }
        for (int k0 = 0; k0 < 128; k0 += 4) {
            float4 a[4];
#pragma unroll
            for (int r = 0; r < 4; r++) a[r] = *(const float4*)&bufA[(r0 + r)*128 + k0];
#pragma unroll
            for (int kk = 0; kk < 4; kk++) {
                const ull* wp = (const ull*)&sW3[(k0+kk)*256 + j0];
                ull w0 = wp[0], w1 = wp[1], w2 = wp[2], w3 = wp[3];
#pragma unroll
                for (int r = 0; r < 4; r++) {
                    float av = (kk==0)?a[r].x:(kk==1)?a[r].y:(kk==2)?a[r].z:a[r].w;
                    ull ap = pack2(av);
                    acc[r][0] = fma2(ap, w0, acc[r][0]);
                    acc[r][1] = fma2(ap, w1, acc[r][1]);
                    acc[r][2] = fma2(ap, w2, acc[r][2]);
                    acc[r][3] = fma2(ap, w3, acc[r][3]);
                }
            }
        }
#pragma unroll
        for (int r = 0; r < 4; r++) {
            ull* dst = (ull*)&bufB[(r0 + r)*256 + j0];
            dst[0] = acc[r][0]; dst[1] = acc[r][1];
            dst[2] = acc[r][2]; dst[3] = acc[r][3];
        }
    }
    __syncthreads();
    ln_rows<256, false, 16>(bufB, ENC_R, g3, be3);
    __syncthreads();

    // mean over K=16 neighbor rows per query
    for (int idx = t; idx < ENC_G * 256; idx += 512) {
        int gq = idx >> 8, j = idx & 255;
        float s = 0.f;
#pragma unroll
        for (int r = 0; r < 16; r++) s += bufB[(gq*16 + r)*256 + j];
        g_agg[(size_t)(q0 + gq)*256 + j] = s * (1.0f/16.0f);
    }
}

// ---------------------------------------------------------------------------
// Kernel 3: aggregator: relu(LN(agg@Wa1+ba1)) @ Wa2 + ba2
// One block = 64 rows, 512 threads, FFMA2 4r x 8c tiles, weights from L2.
// ---------------------------------------------------------------------------
#define AGG_RB 64
#define AGG_SMEM_FLOATS (2 * AGG_RB * 256)

__device__ __forceinline__ void agg_gemm_f2(const float* __restrict__ W,
                                            const float* __restrict__ bias,
                                            const float* src, ull* accOut,
                                            int r0, int j0)
{
    ull acc[4][4];
    {
        const ull* bp = (const ull*)&bias[j0];
#pragma unroll
        for (int r = 0; r < 4; r++) {
            acc[r][0] = bp[0]; acc[r][1] = bp[1];
            acc[r][2] = bp[2]; acc[r][3] = bp[3];
        }
    }
    for (int k0 = 0; k0 < 256; k0 += 4) {
        float4 a[4];
#pragma unroll
        for (int r = 0; r < 4; r++) a[r] = *(const float4*)&src[(r0 + r)*256 + k0];
#pragma unroll
        for (int kk = 0; kk < 4; kk++) {
            const ull* wp = (const ull*)&W[(size_t)(k0+kk)*256 + j0];
            ull w0 = wp[0], w1 = wp[1], w2 = wp[2], w3 = wp[3];
#pragma unroll
            for (int r = 0; r < 4; r++) {
                float av = (kk==0)?a[r].x:(kk==1)?a[r].y:(kk==2)?a[r].z:a[r].w;
                ull ap = pack2(av);
                acc[r][0] = fma2(ap, w0, acc[r][0]);
                acc[r][1] = fma2(ap, w1, acc[r][1]);
                acc[r][2] = fma2(ap, w2, acc[r][2]);
                acc[r][3] = fma2(ap, w3, acc[r][3]);
            }
        }
    }
#pragma unroll
    for (int r = 0; r < 4; r++)
#pragma unroll
        for (int c = 0; c < 4; c++) accOut[r*4+c] = acc[r][c];
}

__global__ __launch_bounds__(512, 1) void agg_kernel(
    const float* __restrict__ Wa1, const float* __restrict__ ba1,
    const float* __restrict__ ga1, const float* __restrict__ bea1,
    const float* __restrict__ Wa2, const float* __restrict__ ba2,
    float* __restrict__ out)
{
    extern __shared__ float sm[];
    float* sin_  = sm;                  // [64][256]
    float* smid  = sm + AGG_RB*256;     // [64][256]
    const int t = threadIdx.x;
    const size_t row0 = (size_t)blockIdx.x * AGG_RB;

    {
        float4* dst = (float4*)sin_;
        const float4* src = (const float4*)(g_agg + row0*256);
        for (int i = t; i < AGG_RB*256/4; i += 512) dst[i] = src[i];
    }
    __syncthreads();

    const int j0 = (t & 31) * 8;
    const int r0 = (t >> 5) * 4;

    {   // stage A
        ull acc[16];
        agg_gemm_f2(Wa1, ba1, sin_, acc, r0, j0);
#pragma unroll
        for (int r = 0; r < 4; r++) {
            ull* dst = (ull*)&smid[(r0 + r)*256 + j0];
#pragma unroll
            for (int c = 0; c < 4; c++) dst[c] = acc[r*4+c];
        }
    }
    __syncthreads();
    ln_rows<256, true, 16>(smid, AGG_RB, ga1, bea1);
    __syncthreads();
    {   // stage B -> out
        ull acc[16];
        agg_gemm_f2(Wa2, ba2, smid, acc, r0, j0);
#pragma unroll
        for (int r = 0; r < 4; r++) {
            ull* dst = (ull*)&out[(row0 + r0 + r)*256 + j0];
#pragma unroll
            for (int c = 0; c < 4; c++) dst[c] = acc[r*4+c];
        }
    }
}

// ---------------------------------------------------------------------------
extern "C" void kernel_launch(void* const* d_in, const int* in_sizes, int n_in,
                              void* d_out, int out_size)
{
    const float* coords = (const float*)d_in[0];
    const float* W1  = (const float*)d_in[1];
    const float* b1  = (const float*)d_in[2];
    const float* g1  = (const float*)d_in[3];
    const float* be1 = (const float*)d_in[4];
    const float* W2  = (const float*)d_in[5];
    const float* b2  = (const float*)d_in[6];
    const float* g2  = (const float*)d_in[7];
    const float* be2 = (const float*)d_in[8];
    const float* W3  = (const float*)d_in[9];
    const float* b3  = (const float*)d_in[10];
    const float* g3  = (const float*)d_in[11];
    const float* be3 = (const float*)d_in[12];
    const float* Wa1 = (const float*)d_in[13];
    const float* ba1 = (const float*)d_in[14];
    const float* ga1 = (const float*)d_in[15];
    const float* bea1= (const float*)d_in[16];
    const float* Wa2 = (const float*)d_in[17];
    const float* ba2 = (const float*)d_in[18];
    float* out = (float*)d_out;

    cudaFuncSetAttribute(encoder_kernel,
                         cudaFuncAttributeMaxDynamicSharedMemorySize,
                         ENC_SMEM_FLOATS * (int)sizeof(float));
    cudaFuncSetAttribute(agg_kernel,
                         cudaFuncAttributeMaxDynamicSharedMemorySize,
                         AGG_SMEM_FLOATS * (int)sizeof(float));

    knn_kernel<<<B_ * (N_ / 64), 256>>>(coords);

    encoder_kernel<<<M_ / ENC_G, 512, ENC_SMEM_FLOATS * sizeof(float)>>>(
        coords, W1, b1, g1, be1, W2, b2, g2, be2, W3, b3, g3, be3);

    agg_kernel<<<M_ / AGG_RB, 512, AGG_SMEM_FLOATS * sizeof(float)>>>(
        Wa1, ba1, ga1, bea1, Wa2, ba2, out);
}

// round 5
// speedup vs baseline: 1.2621x; 1.2621x over previous
#include <cuda_runtime.h>
#include <math.h>

#define B_ 8
#define N_ 4096
#define K_ 16
#define D_ 256
#define M_ (B_*N_)          // 32768 query rows

__device__ int   g_idx[M_*K_];        // 2 MB
__device__ float g_agg[M_*D_];        // 33.5 MB

// ---------------------------------------------------------------------------
// Kernel 1: brute-force kNN, smem-resident candidates (all 4096 points in
// 64KB smem, loaded once -> ONE barrier), 4-way split scan: 4 threads per
// query, 1024 candidates each, no syncs in the scan, 4-way sorted merge.
// 256 threads = 64 queries per block, grid = 512 blocks.
// ---------------------------------------------------------------------------
__global__ __launch_bounds__(256) void knn_kernel(const float* __restrict__ coords)
{
    __shared__ float4 tile[N_];          // 64 KB: all candidates of this batch
    __shared__ float  sd[256 * K_];      // 16 KB
    __shared__ int    si[256 * K_];      // 16 KB

    const int t = threadIdx.x;
    const int b  = blockIdx.x >> 6;                 // 64 blocks per batch
    const int q0 = (blockIdx.x & 63) << 6;          // 64 queries per block
    const int q  = q0 + (t & 63);
    const int split = t >> 6;                       // 0..3
    const float* cb = coords + (size_t)b * N_ * 3;

    // load ALL candidates once (coalesced-ish), precompute |p|^2
    for (int i = t; i < N_; i += 256) {
        float x = cb[i*3+0], y = cb[i*3+1], z = cb[i*3+2];
        tile[i] = make_float4(x, y, z, x*x + y*y + z*z);
    }
    float qx = cb[q*3+0], qy = cb[q*3+1], qz = cb[q*3+2];
    float qsq = qx*qx + qy*qy + qz*qz;
    __syncthreads();

    float best[K_]; int bidx[K_];
#pragma unroll
    for (int s = 0; s < K_; s++) { best[s] = 3.4e38f; bidx[s] = 0; }

    const int base = split * 1024;
    const float4* tl = tile + base;
#pragma unroll 4
    for (int mm = 0; mm < 1024; mm++) {
        float4 c = tl[mm];                          // broadcast within warp
        float d2 = qsq + c.w - 2.0f*(qx*c.x + qy*c.y + qz*c.z);
        if (d2 < best[K_-1]) {
            float d = d2; int id = base + mm;
#pragma unroll
            for (int s = 0; s < K_; s++) {
                if (d < best[s]) {
                    float td = best[s]; int ti = bidx[s];
                    best[s] = d; bidx[s] = id;
                    d = td; id = ti;
                }
            }
        }
    }

#pragma unroll
    for (int s = 0; s < K_; s++) { sd[t*K_ + s] = best[s]; si[t*K_ + s] = bidx[s]; }
    __syncthreads();

    // 4-way merge by threads t < 64 (lexicographic (d2, idx) min = jax tie-break)
    if (t < 64) {
        int ia[4] = {0,0,0,0};
        int* o = g_idx + (size_t)(b*N_ + q0 + t) * K_;
#pragma unroll
        for (int s = 0; s < K_; s++) {
            float bv = 3.5e38f; int bi = 0x7fffffff; int bl = 0;
#pragma unroll
            for (int l = 0; l < 4; l++) {
                int p = ia[l];
                float v  = (p < K_) ? sd[(t + l*64)*K_ + p] : 3.5e38f;
                int   ix = (p < K_) ? si[(t + l*64)*K_ + p] : 0x7fffffff;
                if (v < bv || (v == bv && ix < bi)) { bv = v; bi = ix; bl = l; }
            }
            o[s] = bi;
            ia[bl]++;
        }
    }
}

// ---------------------------------------------------------------------------
// Warp-per-row LayerNorm over smem rows. NW warps in the block.
// ---------------------------------------------------------------------------
template<int W, bool RELU, int NW>
__device__ __forceinline__ void ln_rows(float* buf, int rows,
                                        const float* __restrict__ g,
                                        const float* __restrict__ be)
{
    const int wid = threadIdx.x >> 5, lane = threadIdx.x & 31;
    constexpr int C = W / 32;
    for (int r = wid; r < rows; r += NW) {
        float* h = buf + r * W;
        float v[C]; float s = 0.f;
#pragma unroll
        for (int i = 0; i < C; i++) { v[i] = h[lane + i*32]; s += v[i]; }
#pragma unroll
        for (int o = 16; o; o >>= 1) s += __shfl_xor_sync(0xffffffffu, s, o);
        float mean = s * (1.0f / W);
        float s2 = 0.f;
#pragma unroll
        for (int i = 0; i < C; i++) { float d = v[i] - mean; s2 += d*d; }
#pragma unroll
        for (int o = 16; o; o >>= 1) s2 += __shfl_xor_sync(0xffffffffu, s2, o);
        float rstd = rsqrtf(s2 * (1.0f / W) + 1e-5f);
#pragma unroll
        for (int i = 0; i < C; i++) {
            int c = lane + i*32;
            float o2 = (v[i] - mean) * rstd * g[c] + be[c];
            if (RELU) o2 = fmaxf(o2, 0.f);
            h[c] = o2;
        }
    }
}

__device__ __forceinline__ void fma_j4(float* acc, float a, float4 w) {
    acc[0] = fmaf(a, w.x, acc[0]); acc[1] = fmaf(a, w.y, acc[1]);
    acc[2] = fmaf(a, w.z, acc[2]); acc[3] = fmaf(a, w.w, acc[3]);
}
__device__ __forceinline__ void fma_j2(float* acc, float a, float2 w) {
    acc[0] = fmaf(a, w.x, acc[0]); acc[1] = fmaf(a, w.y, acc[1]);
}

// ---------------------------------------------------------------------------
// Kernel 2: fused geom features + encoder MLP (10->64->128->256) + mean over K
// One block = 4 queries = 64 neighbor rows, 512 threads (16 warps).
// smem: sW3 128KB | bufA 32KB (geom / h2) | bufB 64KB (h1 / h3) = 224KB
// Register tiling: 8 rows x {1,2,4} cols per thread, k unrolled x4, float4.
// (Proven R2 configuration — measured at the scalar-FFMA roofline.)
// ---------------------------------------------------------------------------
#define ENC_G 4
#define ENC_R 64
#define ENC_SMEM_FLOATS (32768 + 8192 + 16384)

__global__ __launch_bounds__(512, 1) void encoder_kernel(
    const float* __restrict__ coords,
    const float* __restrict__ W1, const float* __restrict__ b1,
    const float* __restrict__ g1, const float* __restrict__ be1,
    const float* __restrict__ W2, const float* __restrict__ b2,
    const float* __restrict__ g2, const float* __restrict__ be2,
    const float* __restrict__ W3, const float* __restrict__ b3,
    const float* __restrict__ g3, const float* __restrict__ be3)
{
    extern __shared__ float sm[];
    float* sW3  = sm;                 // 128*256
    float* bufA = sm + 32768;         // 64x128 (geom first, then h2)
    float* bufB = sm + 40960;         // 64x256 (h1 first, then h3)
    const int t = threadIdx.x;
    const int q0 = blockIdx.x * ENC_G;

    {   // stage W3 into smem (consumed in stage 3, after several syncs)
        float4* dst = (float4*)sW3; const float4* src = (const float4*)W3;
        for (int i = t; i < 32768/4; i += 512) dst[i] = src[i];
    }

    if (t < ENC_R) {    // geometric features, one thread per neighbor row
        int q  = q0 + (t >> 4);
        int kk = t & 15;
        int b  = q >> 12;
        int n  = q & (N_ - 1);
        const float* cb = coords + (size_t)b * N_ * 3;
        float qx = cb[n*3+0], qy = cb[n*3+1], qz = cb[n*3+2];
        int nb = g_idx[(size_t)q * K_ + kk];
        float rx = cb[nb*3+0] - qx, ry = cb[nb*3+1] - qy, rz = cb[nb*3+2] - qz;
        float dist = sqrtf(rx*rx + ry*ry + rz*rz);
        float inv  = 1.0f / (dist + 1e-6f);
        float nx = rx*inv, ny = ry*inv, nz = rz*inv;
        float* gm = bufA + t * 10;
        gm[0] = dist; gm[1] = rx; gm[2] = ry; gm[3] = rz;
        gm[4] = atan2f(ny, nx); gm[5] = atan2f(nz, nx); gm[6] = atan2f(nz, ny);
        gm[7] = nx; gm[8] = ny; gm[9] = nz;
    }
    __syncthreads();

    const int chunk = t >> 6;          // 8 row-chunks of 8 rows
    const int r0 = chunk * 8;

    // ---- stage 1: geom[64][10] @ W1[10][64] -> bufB (stride 64) ----
    {
        int j = t & 63;
        float acc[8];
        float bj = b1[j];
#pragma unroll
        for (int r = 0; r < 8; r++) acc[r] = bj;
#pragma unroll
        for (int k = 0; k < 10; k++) {
            float w = W1[k*64 + j];
#pragma unroll
            for (int r = 0; r < 8; r++)
                acc[r] = fmaf(w, bufA[(r0 + r)*10 + k], acc[r]);
        }
#pragma unroll
        for (int r = 0; r < 8; r++) bufB[(r0 + r)*64 + j] = acc[r];
    }
    __syncthreads();
    ln_rows<64, true, 16>(bufB, ENC_R, g1, be1);
    __syncthreads();

    // ---- stage 2: h1[64][64] @ W2[64][128] -> bufA (stride 128) ----
    {
        int j0 = (t & 63) * 2;
        float acc[8][2];
        float2 bj = *(const float2*)&b2[j0];
#pragma unroll
        for (int r = 0; r < 8; r++) { acc[r][0] = bj.x; acc[r][1] = bj.y; }
        for (int k0 = 0; k0 < 64; k0 += 4) {
            float2 w0 = *(const float2*)&W2[(k0+0)*128 + j0];
            float2 w1 = *(const float2*)&W2[(k0+1)*128 + j0];
            float2 w2 = *(const float2*)&W2[(k0+2)*128 + j0];
            float2 w3 = *(const float2*)&W2[(k0+3)*128 + j0];
#pragma unroll
            for (int r = 0; r < 8; r++) {
                float4 a = *(const float4*)&bufB[(r0 + r)*64 + k0];
                fma_j2(acc[r], a.x, w0);
                fma_j2(acc[r], a.y, w1);
                fma_j2(acc[r], a.z, w2);
                fma_j2(acc[r], a.w, w3);
            }
        }
#pragma unroll
        for (int r = 0; r < 8; r++)
            *(float2*)&bufA[(r0 + r)*128 + j0] = make_float2(acc[r][0], acc[r][1]);
    }
    __syncthreads();
    ln_rows<128, true, 16>(bufA, ENC_R, g2, be2);
    __syncthreads();

    // ---- stage 3: h2[64][128] @ W3[128][256] -> bufB (stride 256) ----
    {
        int j0 = (t & 63) * 4;
        float acc[8][4];
        float4 bj = *(const float4*)&b3[j0];
#pragma unroll
        for (int r = 0; r < 8; r++) {
            acc[r][0] = bj.x; acc[r][1] = bj.y; acc[r][2] = bj.z; acc[r][3] = bj.w;
        }
        for (int k0 = 0; k0 < 128; k0 += 4) {
            float4 w0 = *(const float4*)&sW3[(k0+0)*256 + j0];
            float4 w1 = *(const float4*)&sW3[(k0+1)*256 + j0];
            float4 w2 = *(const float4*)&sW3[(k0+2)*256 + j0];
            float4 w3 = *(const float4*)&sW3[(k0+3)*256 + j0];
#pragma unroll
            for (int r = 0; r < 8; r++) {
                float4 a = *(const float4*)&bufA[(r0 + r)*128 + k0];
                fma_j4(acc[r], a.x, w0);
                fma_j4(acc[r], a.y, w1);
                fma_j4(acc[r], a.z, w2);
                fma_j4(acc[r], a.w, w3);
            }
        }
#pragma unroll
        for (int r = 0; r < 8; r++)
            *(float4*)&bufB[(r0 + r)*256 + j0] =
                make_float4(acc[r][0], acc[r][1], acc[r][2], acc[r][3]);
    }
    __syncthreads();
    ln_rows<256, false, 16>(bufB, ENC_R, g3, be3);
    __syncthreads();

    // mean over K=16 neighbor rows per query
    for (int idx = t; idx < ENC_G * 256; idx += 512) {
        int gq = idx >> 8, j = idx & 255;
        float s = 0.f;
#pragma unroll
        for (int r = 0; r < 16; r++) s += bufB[(gq*16 + r)*256 + j];
        g_agg[(size_t)(q0 + gq)*256 + j] = s * (1.0f/16.0f);
    }
}

// ---------------------------------------------------------------------------
// Kernel 3: aggregator: relu(LN(agg@Wa1+ba1)) @ Wa2 + ba2
// One block = 64 rows, 512 threads. smem: 2 * 64*256 floats = 128 KB.
// Tiling: 8 rows x 4 cols per thread, weights streamed from L2 (coalesced).
// (Proven R2 configuration.)
// ---------------------------------------------------------------------------
#define AGG_RB 64
#define AGG_SMEM_FLOATS (2 * AGG_RB * 256)

__global__ __launch_bounds__(512, 1) void agg_kernel(
    const float* __restrict__ Wa1, const float* __restrict__ ba1,
    const float* __restrict__ ga1, const float* __restrict__ bea1,
    const float* __restrict__ Wa2, const float* __restrict__ ba2,
    float* __restrict__ out)
{
    extern __shared__ float sm[];
    float* sin_  = sm;                  // [64][256]
    float* smid  = sm + AGG_RB*256;     // [64][256]
    const int t = threadIdx.x;
    const size_t row0 = (size_t)blockIdx.x * AGG_RB;

    {
        float4* dst = (float4*)sin_;
        const float4* src = (const float4*)(g_agg + row0*256);
        for (int i = t; i < AGG_RB*256/4; i += 512) dst[i] = src[i];
    }
    __syncthreads();

    const int chunk = t >> 6;          // 8 chunks x 8 rows
    const int r0 = chunk * 8;
    const int j0 = (t & 63) * 4;

    {   // stage A: sin @ Wa1 + ba1 -> smid
        float acc[8][4];
        float4 bj = *(const float4*)&ba1[j0];
#pragma unroll
        for (int r = 0; r < 8; r++) {
            acc[r][0] = bj.x; acc[r][1] = bj.y; acc[r][2] = bj.z; acc[r][3] = bj.w;
        }
        for (int k0 = 0; k0 < 256; k0 += 4) {
            float4 w0 = *(const float4*)&Wa1[(size_t)(k0+0)*256 + j0];
            float4 w1 = *(const float4*)&Wa1[(size_t)(k0+1)*256 + j0];
            float4 w2 = *(const float4*)&Wa1[(size_t)(k0+2)*256 + j0];
            float4 w3 = *(const float4*)&Wa1[(size_t)(k0+3)*256 + j0];
#pragma unroll
            for (int r = 0; r < 8; r++) {
                float4 a = *(const float4*)&sin_[(r0 + r)*256 + k0];
                fma_j4(acc[r], a.x, w0);
                fma_j4(acc[r], a.y, w1);
                fma_j4(acc[r], a.z, w2);
                fma_j4(acc[r], a.w, w3);
            }
        }
#pragma unroll
        for (int r = 0; r < 8; r++)
            *(float4*)&smid[(r0 + r)*256 + j0] =
                make_float4(acc[r][0], acc[r][1], acc[r][2], acc[r][3]);
    }
    __syncthreads();
    ln_rows<256, true, 16>(smid, AGG_RB, ga1, bea1);
    __syncthreads();
    {   // stage B: smid @ Wa2 + ba2 -> out
        float acc[8][4];
        float4 bj = *(const float4*)&ba2[j0];
#pragma unroll
        for (int r = 0; r < 8; r++) {
            acc[r][0] = bj.x; acc[r][1] = bj.y; acc[r][2] = bj.z; acc[r][3] = bj.w;
        }
        for (int k0 = 0; k0 < 256; k0 += 4) {
            float4 w0 = *(const float4*)&Wa2[(size_t)(k0+0)*256 + j0];
            float4 w1 = *(const float4*)&Wa2[(size_t)(k0+1)*256 + j0];
            float4 w2 = *(const float4*)&Wa2[(size_t)(k0+2)*256 + j0];
            float4 w3 = *(const float4*)&Wa2[(size_t)(k0+3)*256 + j0];
#pragma unroll
            for (int r = 0; r < 8; r++) {
                float4 a = *(const float4*)&smid[(r0 + r)*256 + k0];
                fma_j4(acc[r], a.x, w0);
                fma_j4(acc[r], a.y, w1);
                fma_j4(acc[r], a.z, w2);
                fma_j4(acc[r], a.w, w3);
            }
        }
#pragma unroll
        for (int r = 0; r < 8; r++)
            *(float4*)&out[(row0 + r0 + r)*256 + j0] =
                make_float4(acc[r][0], acc[r][1], acc[r][2], acc[r][3]);
    }
}

// ---------------------------------------------------------------------------
extern "C" void kernel_launch(void* const* d_in, const int* in_sizes, int n_in,
                              void* d_out, int out_size)
{
    const float* coords = (const float*)d_in[0];
    const float* W1  = (const float*)d_in[1];
    const float* b1  = (const float*)d_in[2];
    const float* g1  = (const float*)d_in[3];
    const float* be1 = (const float*)d_in[4];
    const float* W2  = (const float*)d_in[5];
    const float* b2  = (const float*)d_in[6];
    const float* g2  = (const float*)d_in[7];
    const float* be2 = (const float*)d_in[8];
    const float* W3  = (const float*)d_in[9];
    const float* b3  = (const float*)d_in[10];
    const float* g3  = (const float*)d_in[11];
    const float* be3 = (const float*)d_in[12];
    const float* Wa1 = (const float*)d_in[13];
    const float* ba1 = (const float*)d_in[14];
    const float* ga1 = (const float*)d_in[15];
    const float* bea1= (const float*)d_in[16];
    const float* Wa2 = (const float*)d_in[17];
    const float* ba2 = (const float*)d_in[18];
    float* out = (float*)d_out;

    cudaFuncSetAttribute(encoder_kernel,
                         cudaFuncAttributeMaxDynamicSharedMemorySize,
                         ENC_SMEM_FLOATS * (int)sizeof(float));
    cudaFuncSetAttribute(agg_kernel,
                         cudaFuncAttributeMaxDynamicSharedMemorySize,
                         AGG_SMEM_FLOATS * (int)sizeof(float));

    knn_kernel<<<B_ * (N_ / 64), 256>>>(coords);

    encoder_kernel<<<M_ / ENC_G, 512, ENC_SMEM_FLOATS * sizeof(float)>>>(
        coords, W1, b1, g1, be1, W2, b2, g2, be2, W3, b3, g3, be3);

    agg_kernel<<<M_ / AGG_RB, 512, AGG_SMEM_FLOATS * sizeof(float)>>>(
        Wa1, ba1, ga1, bea1, Wa2, ba2, out);
}

// round 8
// speedup vs baseline: 2.3045x; 1.8259x over previous
#include <cuda_runtime.h>
#include <math.h>
#include <stdint.h>

#define B_ 8
#define N_ 4096
#define K_ 16
#define D_ 256
#define M_ (B_*N_)          // 32768 query rows

__device__ int   g_idx[M_*K_];        // 2 MB
__device__ float g_agg[M_*D_];        // 33.5 MB

// tf32 fragment-major weights (filled by prep_kernel each launch)
__device__ float g_W2f [8*8*32*4];    // [kt8][ntp8][lane32][4]
__device__ float g_W3f [16*16*32*4];  // [kt16][ntp16][lane32][4]
__device__ float g_Wa1f[32*16*32*4];  // [kt32][ntp16][lane32][4]
__device__ float g_Wa2f[32*16*32*4];

// ---------------------------------------------------------------------------
__device__ __forceinline__ float tf32r(float x) {
    uint32_t u;
    asm("cvt.rna.tf32.f32 %0, %1;" : "=r"(u) : "f"(x));
    return __uint_as_float(u);
}
// D += A(m16k8,row) * B(k8n8,col); fp32 accum, tf32 inputs
__device__ __forceinline__ void mma_tf32(float* c, uint4 a, uint32_t b0, uint32_t b1) {
    asm volatile(
        "mma.sync.aligned.m16n8k8.row.col.f32.tf32.tf32.f32 "
        "{%0,%1,%2,%3}, {%4,%5,%6,%7}, {%8,%9}, {%0,%1,%2,%3};"
        : "+f"(c[0]), "+f"(c[1]), "+f"(c[2]), "+f"(c[3])
        : "r"(a.x), "r"(a.y), "r"(a.z), "r"(a.w), "r"(b0), "r"(b1));
}

// ---------------------------------------------------------------------------
// Kernel 0: convert weights to tf32 fragment-major layouts.
// B-frag for (kt, ntile): b0 = W[kt*8+tg][nt*8+g], b1 = W[kt*8+tg+4][nt*8+g]
// stored as float4 [kt][ntpair][lane] = {b0(2p), b1(2p), b0(2p+1), b1(2p+1)}.
// ---------------------------------------------------------------------------
__global__ void prep_kernel(const float* __restrict__ W2, const float* __restrict__ W3,
                            const float* __restrict__ Wa1, const float* __restrict__ Wa2)
{
    int idx = blockIdx.x * 256 + threadIdx.x;   // 43008 total float4 entries
    const float* W; float* dst; int NT, NTP, kt, ntp, lane, go;
    if (idx < 2048)        { int r = idx;          W = W2;  dst = g_W2f;  NT = 128; NTP = 8; }
    else if (idx < 10240)  { int r = idx - 2048;   W = W3;  dst = g_W3f;  NT = 256; NTP = 16; idx = r + 2048; }
    else if (idx < 26624)  { }
    else if (idx < 43008)  { }
    else return;
    // decode per-region (recompute cleanly)
    int r;
    if (idx < 2048)       { r = idx;         W = W2;  dst = g_W2f;  NT = 128; NTP = 8;  }
    else if (idx < 10240) { r = idx - 2048;  W = W3;  dst = g_W3f;  NT = 256; NTP = 16; }
    else if (idx < 26624) { r = idx - 10240; W = Wa1; dst = g_Wa1f; NT = 256; NTP = 16; }
    else                  { r = idx - 26624; W = Wa2; dst = g_Wa2f; NT = 256; NTP = 16; }
    lane = r & 31; ntp = (r >> 5) % NTP; kt = (r >> 5) / NTP;
    int g = lane >> 2, tg = lane & 3;
    int nt0 = 2*ntp, nt1 = 2*ntp + 1;
    float4 v;
    v.x = tf32r(W[(kt*8 + tg    )*NT + nt0*8 + g]);
    v.y = tf32r(W[(kt*8 + tg + 4)*NT + nt0*8 + g]);
    v.z = tf32r(W[(kt*8 + tg    )*NT + nt1*8 + g]);
    v.w = tf32r(W[(kt*8 + tg + 4)*NT + nt1*8 + g]);
    go = (kt*NTP + ntp)*32 + lane;
    ((float4*)dst)[go] = v;
}

// ---------------------------------------------------------------------------
// Kernel 1: brute-force kNN — exact R2 configuration (measured 422us).
// 2-way split scan, 256 threads = 128 queries per block.
// ---------------------------------------------------------------------------
__global__ __launch_bounds__(256) void knn_kernel(const float* __restrict__ coords)
{
    __shared__ float4 tile[256];
    __shared__ float  sd[256 * K_];
    __shared__ int    si[256 * K_];

    const int t = threadIdx.x;
    const int b  = blockIdx.x >> 5;
    const int q0 = (blockIdx.x & 31) << 7;
    const int q  = q0 + (t & 127);
    const int half = t >> 7;
    const float* cb = coords + (size_t)b * N_ * 3;

    float qx = cb[q*3+0], qy = cb[q*3+1], qz = cb[q*3+2];
    float qsq = qx*qx + qy*qy + qz*qz;

    float best[K_]; int bidx[K_];
#pragma unroll
    for (int s = 0; s < K_; s++) { best[s] = 3.4e38f; bidx[s] = 0; }

    const int base = half * 2048;
    for (int c0 = 0; c0 < 2048; c0 += 128) {
        __syncthreads();
        {
            int m = (t < 128) ? (c0 + t) : (2048 + c0 + (t - 128));
            float x = cb[m*3+0], y = cb[m*3+1], z = cb[m*3+2];
            tile[t] = make_float4(x, y, z, x*x + y*y + z*z);
        }
        __syncthreads();
        const float4* tl = tile + half * 128;
#pragma unroll 4
        for (int mm = 0; mm < 128; mm++) {
            float4 c = tl[mm];
            float d2 = qsq + c.w - 2.0f*(qx*c.x + qy*c.y + qz*c.z);
            if (d2 < best[K_-1]) {
                float d = d2; int id = base + c0 + mm;
#pragma unroll
                for (int s = 0; s < K_; s++) {
                    if (d < best[s]) {
                        float td = best[s]; int ti = bidx[s];
                        best[s] = d; bidx[s] = id;
                        d = td; id = ti;
                    }
                }
            }
        }
    }

#pragma unroll
    for (int s = 0; s < K_; s++) { sd[t*K_ + s] = best[s]; si[t*K_ + s] = bidx[s]; }
    __syncthreads();

    if (t < 128) {
        const float* da = sd + t*K_;        const int* xa = si + t*K_;
        const float* db = sd + (t+128)*K_;  const int* xb = si + (t+128)*K_;
        int ia = 0, ib = 0;
        int* o = g_idx + (size_t)(b*N_ + q0 + t) * K_;
#pragma unroll
        for (int s = 0; s < K_; s++) {
            float va = (ia < K_) ? da[ia] : 3.4e38f;
            float vb = (ib < K_) ? db[ib] : 3.4e38f;
            bool takeA = (va < vb) || (va == vb && ((ia < K_ ? xa[ia] : 0x7fffffff) <
                                                    (ib < K_ ? xb[ib] : 0x7fffffff)));
            if (takeA) { o[s] = xa[ia]; ia++; }
            else       { o[s] = xb[ib]; ib++; }
        }
    }
}

// ---------------------------------------------------------------------------
// Warp-per-row LayerNorm with runtime row stride. NW warps per block.
// ---------------------------------------------------------------------------
template<int W, bool RELU, int NW>
__device__ __forceinline__ void ln_rows_s(float* buf, int stride, int rows,
                                          const float* __restrict__ g,
                                          const float* __restrict__ be)
{
    const int wid = threadIdx.x >> 5, lane = threadIdx.x & 31;
    constexpr int C = W / 32;
    for (int r = wid; r < rows; r += NW) {
        float* h = buf + r * stride;
        float v[C]; float s = 0.f;
#pragma unroll
        for (int i = 0; i < C; i++) { v[i] = h[lane + i*32]; s += v[i]; }
#pragma unroll
        for (int o = 16; o; o >>= 1) s += __shfl_xor_sync(0xffffffffu, s, o);
        float mean = s * (1.0f / W);
        float s2 = 0.f;
#pragma unroll
        for (int i = 0; i < C; i++) { float d = v[i] - mean; s2 += d*d; }
#pragma unroll
        for (int o = 16; o; o >>= 1) s2 += __shfl_xor_sync(0xffffffffu, s2, o);
        float rstd = rsqrtf(s2 * (1.0f / W) + 1e-5f);
#pragma unroll
        for (int i = 0; i < C; i++) {
            int c = lane + i*32;
            float o2 = (v[i] - mean) * rstd * g[c] + be[c];
            if (RELU) o2 = fmaxf(o2, 0.f);
            h[c] = o2;
        }
    }
}

// cvt a fp32 smem matrix (rows x cols, given stride) into A-fragment-major tf32:
// dstATF float4-entry index ((kt*4 + mtile)*32 + lane), j in 0..3:
//   row = mtile*16 + (lane>>2) + (j&1)*8 ; col = kt*8 + (lane&3) + ((j>>1)&1)*4
template<int KT>
__device__ __forceinline__ void cvt_to_afrag(const float* src, int sstride,
                                             float* dstATF, int tid, int nthr)
{
    const int total = KT * 4 * 32 * 4;
    for (int idx = tid; idx < total; idx += nthr) {
        int j    = idx & 3;
        int lane = (idx >> 2) & 31;
        int mt   = (idx >> 7) & 3;
        int kt   = idx >> 9;
        int row  = mt*16 + (lane >> 2) + (j & 1)*8;
        int col  = kt*8 + (lane & 3) + ((j >> 1) & 1)*4;
        dstATF[idx] = tf32r(src[row*sstride + col]);
    }
}

// ---------------------------------------------------------------------------
// Kernel 2: fused geom features + encoder MLP (10->64->128->256) + mean over K
// One block = 4 queries = 64 rows, 512 threads (16 warps).
// Stage 1 fp32 scalar; stages 2,3 tf32 mma (m16n8k8), fp32 accumulation.
// smem floats: sW3f[32768] | bufF[16640] | sATF[8192]  = 230400 B
// ---------------------------------------------------------------------------
#define ENC_G 4
#define ENC_R 64
#define ENC_SMEM_FLOATS (32768 + 16640 + 8192)

__global__ __launch_bounds__(512, 1) void encoder_kernel(
    const float* __restrict__ coords,
    const float* __restrict__ W1, const float* __restrict__ b1,
    const float* __restrict__ g1, const float* __restrict__ be1,
    const float* __restrict__ b2,
    const float* __restrict__ g2, const float* __restrict__ be2,
    const float* __restrict__ b3,
    const float* __restrict__ g3, const float* __restrict__ be3)
{
    extern __shared__ float sm[];
    float* sW3f = sm;                  // 32768
    float* bufF = sm + 32768;          // 16640 (stride 64 / 136 / 260 over time)
    float* sATF = sm + 32768 + 16640;  // 8192 (geom first, then A-fragments)
    const int t = threadIdx.x;
    const int w = t >> 5;
    const int lane = t & 31;
    const int g = lane >> 2, tg = lane & 3;
    const int q0 = blockIdx.x * ENC_G;

    {   // stage W3 fragments into smem
        float4* dst = (float4*)sW3f; const float4* src = (const float4*)g_W3f;
        for (int i = t; i < 32768/4; i += 512) dst[i] = src[i];
    }

    if (t < ENC_R) {    // geometric features -> sATF[t*10..]
        int q  = q0 + (t >> 4);
        int kk = t & 15;
        int b  = q >> 12;
        int n  = q & (N_ - 1);
        const float* cb = coords + (size_t)b * N_ * 3;
        float qx = cb[n*3+0], qy = cb[n*3+1], qz = cb[n*3+2];
        int nb = g_idx[(size_t)q * K_ + kk];
        float rx = cb[nb*3+0] - qx, ry = cb[nb*3+1] - qy, rz = cb[nb*3+2] - qz;
        float dist = sqrtf(rx*rx + ry*ry + rz*rz);
        float inv  = 1.0f / (dist + 1e-6f);
        float nx = rx*inv, ny = ry*inv, nz = rz*inv;
        float* gm = sATF + t * 10;
        gm[0] = dist; gm[1] = rx; gm[2] = ry; gm[3] = rz;
        gm[4] = atan2f(ny, nx); gm[5] = atan2f(nz, nx); gm[6] = atan2f(nz, ny);
        gm[7] = nx; gm[8] = ny; gm[9] = nz;
    }
    __syncthreads();

    // ---- stage 1 (fp32): geom[64][10] @ W1[10][64] -> bufF stride 64 ----
    {
        int j = t & 63, r0 = (t >> 6) * 8;
        float acc[8];
        float bj = b1[j];
#pragma unroll
        for (int r = 0; r < 8; r++) acc[r] = bj;
#pragma unroll
        for (int k = 0; k < 10; k++) {
            float wv = W1[k*64 + j];
#pragma unroll
            for (int r = 0; r < 8; r++)
                acc[r] = fmaf(wv, sATF[(r0 + r)*10 + k], acc[r]);
        }
#pragma unroll
        for (int r = 0; r < 8; r++) bufF[(r0 + r)*64 + j] = acc[r];
    }
    __syncthreads();
    ln_rows_s<64, true, 16>(bufF, 64, ENC_R, g1, be1);
    __syncthreads();

    // cvt h1 -> A-fragments (K=64 -> KT=8)
    cvt_to_afrag<8>(bufF, 64, sATF, t, 512);
    __syncthreads();

    // ---- stage 2 (mma): h1[64x64] @ W2[64x128] -> bufF stride 136 ----
    {
        const int mt2 = w & 1;           // mtiles {2*mt2, 2*mt2+1}
        const int ntp = w >> 1;          // ntiles {2*ntp, 2*ntp+1}
        float acc[2][2][4];
#pragma unroll
        for (int a = 0; a < 2; a++)
#pragma unroll
            for (int c = 0; c < 2; c++)
#pragma unroll
                for (int k = 0; k < 4; k++) acc[a][c][k] = 0.f;
        const uint4* AT = (const uint4*)sATF;
        const uint4* BT = (const uint4*)g_W2f;
#pragma unroll
        for (int kt = 0; kt < 8; kt++) {
            uint4 a0 = AT[(kt*4 + mt2*2    )*32 + lane];
            uint4 a1 = AT[(kt*4 + mt2*2 + 1)*32 + lane];
            uint4 bq = BT[(kt*8 + ntp)*32 + lane];
            mma_tf32(acc[0][0], a0, bq.x, bq.y);
            mma_tf32(acc[0][1], a0, bq.z, bq.w);
            mma_tf32(acc[1][0], a1, bq.x, bq.y);
            mma_tf32(acc[1][1], a1, bq.z, bq.w);
        }
#pragma unroll
        for (int a = 0; a < 2; a++) {
            int row = (mt2*2 + a)*16 + g;
#pragma unroll
            for (int c = 0; c < 2; c++) {
                int col = (2*ntp + c)*8 + 2*tg;
                float2 bb = *(const float2*)&b2[col];
                *(float2*)&bufF[ row     *136 + col] =
                    make_float2(acc[a][c][0] + bb.x, acc[a][c][1] + bb.y);
                *(float2*)&bufF[(row + 8)*136 + col] =
                    make_float2(acc[a][c][2] + bb.x, acc[a][c][3] + bb.y);
            }
        }
    }
    __syncthreads();
    ln_rows_s<128, true, 16>(bufF, 136, ENC_R, g2, be2);
    __syncthreads();

    // cvt h2 -> A-fragments (K=128 -> KT=16)
    cvt_to_afrag<16>(bufF, 136, sATF, t, 512);
    __syncthreads();

    // ---- stage 3 (mma): h2[64x128] @ W3[128x256] -> bufF stride 260 ----
    {
        const int mt2 = w & 1;           // mtiles {2*mt2, 2*mt2+1}
        const int ng  = w >> 1;          // ntiles {4ng .. 4ng+3} (ntpairs 2ng, 2ng+1)
        float acc[2][4][4];
#pragma unroll
        for (int a = 0; a < 2; a++)
#pragma unroll
            for (int c = 0; c < 4; c++)
#pragma unroll
                for (int k = 0; k < 4; k++) acc[a][c][k] = 0.f;
        const uint4* AT = (const uint4*)sATF;
        const uint4* BT = (const uint4*)sW3f;
#pragma unroll
        for (int kt = 0; kt < 16; kt++) {
            uint4 a0 = AT[(kt*4 + mt2*2    )*32 + lane];
            uint4 a1 = AT[(kt*4 + mt2*2 + 1)*32 + lane];
            uint4 bq0 = BT[(kt*16 + 2*ng    )*32 + lane];
            uint4 bq1 = BT[(kt*16 + 2*ng + 1)*32 + lane];
            mma_tf32(acc[0][0], a0, bq0.x, bq0.y);
            mma_tf32(acc[0][1], a0, bq0.z, bq0.w);
            mma_tf32(acc[0][2], a0, bq1.x, bq1.y);
            mma_tf32(acc[0][3], a0, bq1.z, bq1.w);
            mma_tf32(acc[1][0], a1, bq0.x, bq0.y);
            mma_tf32(acc[1][1], a1, bq0.z, bq0.w);
            mma_tf32(acc[1][2], a1, bq1.x, bq1.y);
            mma_tf32(acc[1][3], a1, bq1.z, bq1.w);
        }
#pragma unroll
        for (int a = 0; a < 2; a++) {
            int row = (mt2*2 + a)*16 + g;
#pragma unroll
            for (int c = 0; c < 4; c++) {
                int col = (4*ng + c)*8 + 2*tg;
                float2 bb = *(const float2*)&b3[col];
                *(float2*)&bufF[ row     *260 + col] =
                    make_float2(acc[a][c][0] + bb.x, acc[a][c][1] + bb.y);
                *(float2*)&bufF[(row + 8)*260 + col] =
                    make_float2(acc[a][c][2] + bb.x, acc[a][c][3] + bb.y);
            }
        }
    }
    __syncthreads();
    ln_rows_s<256, false, 16>(bufF, 260, ENC_R, g3, be3);
    __syncthreads();

    // mean over K=16 neighbor rows per query
    for (int idx = t; idx < ENC_G * 256; idx += 512) {
        int gq = idx >> 8, j = idx & 255;
        float s = 0.f;
#pragma unroll
        for (int r = 0; r < 16; r++) s += bufF[(gq*16 + r)*260 + j];
        g_agg[(size_t)(q0 + gq)*256 + j] = s * (1.0f/16.0f);
    }
}

// ---------------------------------------------------------------------------
// Kernel 3: aggregator via tf32 mma: relu(LN(agg@Wa1+ba1)) @ Wa2 + ba2
// One block = 64 rows, 512 threads. smem: ATF 16384 + bufF 16640 floats.
// ---------------------------------------------------------------------------
#define AGG_RB 64
#define AGG_SMEM_FLOATS (16384 + 16640)

__global__ __launch_bounds__(512, 1) void agg_kernel(
    const float* __restrict__ ba1,
    const float* __restrict__ ga1, const float* __restrict__ bea1,
    const float* __restrict__ ba2,
    float* __restrict__ out)
{
    extern __shared__ float sm[];
    float* sATF = sm;            // 16384: A fragments (KT=32)
    float* bufF = sm + 16384;    // 16640
    const int t = threadIdx.x;
    const int w = t >> 5;
    const int lane = t & 31;
    const int g = lane >> 2, tg = lane & 3;
    const size_t row0 = (size_t)blockIdx.x * AGG_RB;

    {   // load input rows fp32 (coalesced), then cvt to fragments
        float4* dst = (float4*)bufF;
        const float4* src = (const float4*)(g_agg + row0*256);
        for (int i = t; i < AGG_RB*256/4; i += 512) dst[i] = src[i];
    }
    __syncthreads();
    cvt_to_afrag<32>(bufF, 256, sATF, t, 512);
    __syncthreads();

    const int mt2 = w & 1;
    const int ng  = w >> 1;

    // ---- stage A: in @ Wa1 + ba1 -> bufF stride 260 ----
    {
        float acc[2][4][4];
#pragma unroll
        for (int a = 0; a < 2; a++)
#pragma unroll
            for (int c = 0; c < 4; c++)
#pragma unroll
                for (int k = 0; k < 4; k++) acc[a][c][k] = 0.f;
        const uint4* AT = (const uint4*)sATF;
        const uint4* BT = (const uint4*)g_Wa1f;
#pragma unroll 8
        for (int kt = 0; kt < 32; kt++) {
            uint4 a0 = AT[(kt*4 + mt2*2    )*32 + lane];
            uint4 a1 = AT[(kt*4 + mt2*2 + 1)*32 + lane];
            uint4 bq0 = BT[(kt*16 + 2*ng    )*32 + lane];
            uint4 bq1 = BT[(kt*16 + 2*ng + 1)*32 + lane];
            mma_tf32(acc[0][0], a0, bq0.x, bq0.y);
            mma_tf32(acc[0][1], a0, bq0.z, bq0.w);
            mma_tf32(acc[0][2], a0, bq1.x, bq1.y);
            mma_tf32(acc[0][3], a0, bq1.z, bq1.w);
            mma_tf32(acc[1][0], a1, bq0.x, bq0.y);
            mma_tf32(acc[1][1], a1, bq0.z, bq0.w);
            mma_tf32(acc[1][2], a1, bq1.x, bq1.y);
            mma_tf32(acc[1][3], a1, bq1.z, bq1.w);
        }
#pragma unroll
        for (int a = 0; a < 2; a++) {
            int row = (mt2*2 + a)*16 + g;
#pragma unroll
            for (int c = 0; c < 4; c++) {
                int col = (4*ng + c)*8 + 2*tg;
                float2 bb = *(const float2*)&ba1[col];
                *(float2*)&bufF[ row     *260 + col] =
                    make_float2(acc[a][c][0] + bb.x, acc[a][c][1] + bb.y);
                *(float2*)&bufF[(row + 8)*260 + col] =
                    make_float2(acc[a][c][2] + bb.x, acc[a][c][3] + bb.y);
            }
        }
    }
    __syncthreads();
    ln_rows_s<256, true, 16>(bufF, 260, AGG_RB, ga1, bea1);
    __syncthreads();
    cvt_to_afrag<32>(bufF, 260, sATF, t, 512);
    __syncthreads();

    // ---- stage B: mid @ Wa2 + ba2 -> out (direct from fragments) ----
    {
        float acc[2][4][4];
#pragma unroll
        for (int a = 0; a < 2; a++)
#pragma unroll
            for (int c = 0; c < 4; c++)
#pragma unroll
                for (int k = 0; k < 4; k++) acc[a][c][k] = 0.f;
        const uint4* AT = (const uint4*)sATF;
        const uint4* BT = (const uint4*)g_Wa2f;
#pragma unroll 8
        for (int kt = 0; kt < 32; kt++) {
            uint4 a0 = AT[(kt*4 + mt2*2    )*32 + lane];
            uint4 a1 = AT[(kt*4 + mt2*2 + 1)*32 + lane];
            uint4 bq0 = BT[(kt*16 + 2*ng    )*32 + lane];
            uint4 bq1 = BT[(kt*16 + 2*ng + 1)*32 + lane];
            mma_tf32(acc[0][0], a0, bq0.x, bq0.y);
            mma_tf32(acc[0][1], a0, bq0.z, bq0.w);
            mma_tf32(acc[0][2], a0, bq1.x, bq1.y);
            mma_tf32(acc[0][3], a0, bq1.z, bq1.w);
            mma_tf32(acc[1][0], a1, bq0.x, bq0.y);
            mma_tf32(acc[1][1], a1, bq0.z, bq0.w);
            mma_tf32(acc[1][2], a1, bq1.x, bq1.y);
            mma_tf32(acc[1][3], a1, bq1.z, bq1.w);
        }
#pragma unroll
        for (int a = 0; a < 2; a++) {
            size_t row = row0 + (mt2*2 + a)*16 + g;
#pragma unroll
            for (int c = 0; c < 4; c++) {
                int col = (4*ng + c)*8 + 2*tg;
                float2 bb = *(const float2*)&ba2[col];
                *(float2*)&out[ row     *256 + col] =
                    make_float2(acc[a][c][0] + bb.x, acc[a][c][1] + bb.y);
                *(float2*)&out[(row + 8)*256 + col] =
                    make_float2(acc[a][c][2] + bb.x, acc[a][c][3] + bb.y);
            }
        }
    }
}

// ---------------------------------------------------------------------------
extern "C" void kernel_launch(void* const* d_in, const int* in_sizes, int n_in,
                              void* d_out, int out_size)
{
    const float* coords = (const float*)d_in[0];
    const float* W1  = (const float*)d_in[1];
    const float* b1  = (const float*)d_in[2];
    const float* g1  = (const float*)d_in[3];
    const float* be1 = (const float*)d_in[4];
    const float* W2  = (const float*)d_in[5];
    const float* b2  = (const float*)d_in[6];
    const float* g2  = (const float*)d_in[7];
    const float* be2 = (const float*)d_in[8];
    const float* W3  = (const float*)d_in[9];
    const float* b3  = (const float*)d_in[10];
    const float* g3  = (const float*)d_in[11];
    const float* be3 = (const float*)d_in[12];
    const float* Wa1 = (const float*)d_in[13];
    const float* ba1 = (const float*)d_in[14];
    const float* ga1 = (const float*)d_in[15];
    const float* bea1= (const float*)d_in[16];
    const float* Wa2 = (const float*)d_in[17];
    const float* ba2 = (const float*)d_in[18];
    float* out = (float*)d_out;

    cudaFuncSetAttribute(encoder_kernel,
                         cudaFuncAttributeMaxDynamicSharedMemorySize,
                         ENC_SMEM_FLOATS * (int)sizeof(float));
    cudaFuncSetAttribute(agg_kernel,
                         cudaFuncAttributeMaxDynamicSharedMemorySize,
                         AGG_SMEM_FLOATS * (int)sizeof(float));

    prep_kernel<<<(43008 + 255)/256, 256>>>(W2, W3, Wa1, Wa2);

    knn_kernel<<<B_ * (N_ / 128), 256>>>(coords);

    encoder_kernel<<<M_ / ENC_G, 512, ENC_SMEM_FLOATS * sizeof(float)>>>(
        coords, W1, b1, g1, be1, b2, g2, be2, b3, g3, be3);

    agg_kernel<<<M_ / AGG_RB, 512, AGG_SMEM_FLOATS * sizeof(float)>>>(
        ba1, ga1, bea1, ba2, out);
}

// round 9
// speedup vs baseline: 2.8315x; 1.2287x over previous
#include <cuda_runtime.h>
#include <math.h>
#include <stdint.h>

#define B_ 8
#define N_ 4096
#define K_ 16
#define D_ 256
#define M_ (B_*N_)          // 32768 query rows

__device__ int   g_idx[M_*K_];        // 2 MB
__device__ float g_agg[M_*D_];        // 33.5 MB

// tf32 fragment-major weights (filled by prep_kernel each launch)
__device__ float g_W2f [8*8*32*4];    // [kt8][ntp8][lane32][4]
__device__ float g_W3f [16*16*32*4];  // [kt16][ntp16][lane32][4]
__device__ float g_Wa1f[32*16*32*4];  // [kt32][ntp16][lane32][4]
__device__ float g_Wa2f[32*16*32*4];

// ---------------------------------------------------------------------------
__device__ __forceinline__ float tf32r(float x) {
    uint32_t u;
    asm("cvt.rna.tf32.f32 %0, %1;" : "=r"(u) : "f"(x));
    return __uint_as_float(u);
}
// D += A(m16k8,row) * B(k8n8,col); fp32 accum, tf32 inputs
__device__ __forceinline__ void mma_tf32(float* c, uint4 a, uint32_t b0, uint32_t b1) {
    asm volatile(
        "mma.sync.aligned.m16n8k8.row.col.f32.tf32.tf32.f32 "
        "{%0,%1,%2,%3}, {%4,%5,%6,%7}, {%8,%9}, {%0,%1,%2,%3};"
        : "+f"(c[0]), "+f"(c[1]), "+f"(c[2]), "+f"(c[3])
        : "r"(a.x), "r"(a.y), "r"(a.z), "r"(a.w), "r"(b0), "r"(b1));
}

// ---------------------------------------------------------------------------
// Kernel 0: convert weights to tf32 fragment-major layouts.
// ---------------------------------------------------------------------------
__global__ void prep_kernel(const float* __restrict__ W2, const float* __restrict__ W3,
                            const float* __restrict__ Wa1, const float* __restrict__ Wa2)
{
    int idx = blockIdx.x * 256 + threadIdx.x;   // 43008 total float4 entries
    if (idx >= 43008) return;
    const float* W; float* dst; int NT, NTP, r;
    if (idx < 2048)       { r = idx;         W = W2;  dst = g_W2f;  NT = 128; NTP = 8;  }
    else if (idx < 10240) { r = idx - 2048;  W = W3;  dst = g_W3f;  NT = 256; NTP = 16; }
    else if (idx < 26624) { r = idx - 10240; W = Wa1; dst = g_Wa1f; NT = 256; NTP = 16; }
    else                  { r = idx - 26624; W = Wa2; dst = g_Wa2f; NT = 256; NTP = 16; }
    int lane = r & 31, ntp = (r >> 5) % NTP, kt = (r >> 5) / NTP;
    int g = lane >> 2, tg = lane & 3;
    int nt0 = 2*ntp, nt1 = 2*ntp + 1;
    float4 v;
    v.x = tf32r(W[(kt*8 + tg    )*NT + nt0*8 + g]);
    v.y = tf32r(W[(kt*8 + tg + 4)*NT + nt0*8 + g]);
    v.z = tf32r(W[(kt*8 + tg    )*NT + nt1*8 + g]);
    v.w = tf32r(W[(kt*8 + tg + 4)*NT + nt1*8 + g]);
    ((float4*)dst)[(kt*NTP + ntp)*32 + lane] = v;
}

// ---------------------------------------------------------------------------
// Kernel 1: brute-force kNN — measured-optimal R2 configuration.
// ---------------------------------------------------------------------------
__global__ __launch_bounds__(256) void knn_kernel(const float* __restrict__ coords)
{
    __shared__ float4 tile[256];
    __shared__ float  sd[256 * K_];
    __shared__ int    si[256 * K_];

    const int t = threadIdx.x;
    const int b  = blockIdx.x >> 5;
    const int q0 = (blockIdx.x & 31) << 7;
    const int q  = q0 + (t & 127);
    const int half = t >> 7;
    const float* cb = coords + (size_t)b * N_ * 3;

    float qx = cb[q*3+0], qy = cb[q*3+1], qz = cb[q*3+2];
    float qsq = qx*qx + qy*qy + qz*qz;

    float best[K_]; int bidx[K_];
#pragma unroll
    for (int s = 0; s < K_; s++) { best[s] = 3.4e38f; bidx[s] = 0; }

    const int base = half * 2048;
    for (int c0 = 0; c0 < 2048; c0 += 128) {
        __syncthreads();
        {
            int m = (t < 128) ? (c0 + t) : (2048 + c0 + (t - 128));
            float x = cb[m*3+0], y = cb[m*3+1], z = cb[m*3+2];
            tile[t] = make_float4(x, y, z, x*x + y*y + z*z);
        }
        __syncthreads();
        const float4* tl = tile + half * 128;
#pragma unroll 4
        for (int mm = 0; mm < 128; mm++) {
            float4 c = tl[mm];
            float d2 = qsq + c.w - 2.0f*(qx*c.x + qy*c.y + qz*c.z);
            if (d2 < best[K_-1]) {
                float d = d2; int id = base + c0 + mm;
#pragma unroll
                for (int s = 0; s < K_; s++) {
                    if (d < best[s]) {
                        float td = best[s]; int ti = bidx[s];
                        best[s] = d; bidx[s] = id;
                        d = td; id = ti;
                    }
                }
            }
        }
    }

#pragma unroll
    for (int s = 0; s < K_; s++) { sd[t*K_ + s] = best[s]; si[t*K_ + s] = bidx[s]; }
    __syncthreads();

    if (t < 128) {
        const float* da = sd + t*K_;        const int* xa = si + t*K_;
        const float* db = sd + (t+128)*K_;  const int* xb = si + (t+128)*K_;
        int ia = 0, ib = 0;
        int* o = g_idx + (size_t)(b*N_ + q0 + t) * K_;
#pragma unroll
        for (int s = 0; s < K_; s++) {
            float va = (ia < K_) ? da[ia] : 3.4e38f;
            float vb = (ib < K_) ? db[ib] : 3.4e38f;
            bool takeA = (va < vb) || (va == vb && ((ia < K_ ? xa[ia] : 0x7fffffff) <
                                                    (ib < K_ ? xb[ib] : 0x7fffffff)));
            if (takeA) { o[s] = xa[ia]; ia++; }
            else       { o[s] = xb[ib]; ib++; }
        }
    }
}

// ---------------------------------------------------------------------------
// Warp-per-row LayerNorm with runtime row stride. NW warps per block.
// ---------------------------------------------------------------------------
template<int W, bool RELU, int NW>
__device__ __forceinline__ void ln_rows_s(float* buf, int stride, int rows,
                                          const float* __restrict__ g,
                                          const float* __restrict__ be)
{
    const int wid = threadIdx.x >> 5, lane = threadIdx.x & 31;
    constexpr int C = W / 32;
    for (int r = wid; r < rows; r += NW) {
        float* h = buf + r * stride;
        float v[C]; float s = 0.f;
#pragma unroll
        for (int i = 0; i < C; i++) { v[i] = h[lane + i*32]; s += v[i]; }
#pragma unroll
        for (int o = 16; o; o >>= 1) s += __shfl_xor_sync(0xffffffffu, s, o);
        float mean = s * (1.0f / W);
        float s2 = 0.f;
#pragma unroll
        for (int i = 0; i < C; i++) { float d = v[i] - mean; s2 += d*d; }
#pragma unroll
        for (int o = 16; o; o >>= 1) s2 += __shfl_xor_sync(0xffffffffu, s2, o);
        float rstd = rsqrtf(s2 * (1.0f / W) + 1e-5f);
#pragma unroll
        for (int i = 0; i < C; i++) {
            int c = lane + i*32;
            float o2 = (v[i] - mean) * rstd * g[c] + be[c];
            if (RELU) o2 = fmaxf(o2, 0.f);
            h[c] = o2;
        }
    }
}

// cvt fp32 smem matrix (16*MT rows x KT*8 cols, stride) -> A-fragment tf32.
// float index ((kt*MT + mt)*32 + lane)*4 + j:
//   row = mt*16 + (lane>>2) + (j&1)*8 ; col = kt*8 + (lane&3) + ((j>>1)&1)*4
template<int KT, int MT>
__device__ __forceinline__ void cvt_to_afrag(const float* src, int sstride,
                                             float* dstATF, int tid, int nthr)
{
    const int total = KT * MT * 32 * 4;
    for (int idx = tid; idx < total; idx += nthr) {
        int j    = idx & 3;
        int lane = (idx >> 2) & 31;
        int mt   = (idx >> 7) % MT;
        int kt   = (idx >> 7) / MT;
        int row  = mt*16 + (lane >> 2) + (j & 1)*8;
        int col  = kt*8 + (lane & 3) + ((j >> 1) & 1)*4;
        dstATF[idx] = tf32r(src[row*sstride + col]);
    }
}

// ---------------------------------------------------------------------------
// Kernel 2: fused geom features + encoder MLP (10->64->128->256) + mean over K
// One block = 8 queries = 128 rows, 512 threads (16 warps).
// Stage 1 fp32 scalar; stages 2,3 tf32 mma, B-fragments streamed from L2.
// smem floats: bufF[33280] | sATF[16384] = 198656 B
// ---------------------------------------------------------------------------
#define ENC_G 8
#define ENC_R 128
#define ENC_SMEM_FLOATS (33280 + 16384)

__global__ __launch_bounds__(512, 1) void encoder_kernel(
    const float* __restrict__ coords,
    const float* __restrict__ W1, const float* __restrict__ b1,
    const float* __restrict__ g1, const float* __restrict__ be1,
    const float* __restrict__ b2,
    const float* __restrict__ g2, const float* __restrict__ be2,
    const float* __restrict__ b3,
    const float* __restrict__ g3, const float* __restrict__ be3)
{
    extern __shared__ float sm[];
    float* bufF = sm;                  // 33280 (stride 64 / 136 / 260 over time)
    float* sATF = sm + 33280;          // 16384 (geom first, then A-fragments)
    const int t = threadIdx.x;
    const int w = t >> 5;
    const int lane = t & 31;
    const int g = lane >> 2, tg = lane & 3;
    const int q0 = blockIdx.x * ENC_G;

    if (t < ENC_R) {    // geometric features -> sATF[t*10..]
        int q  = q0 + (t >> 4);
        int kk = t & 15;
        int b  = q >> 12;
        int n  = q & (N_ - 1);
        const float* cb = coords + (size_t)b * N_ * 3;
        float qx = cb[n*3+0], qy = cb[n*3+1], qz = cb[n*3+2];
        int nb = g_idx[(size_t)q * K_ + kk];
        float rx = cb[nb*3+0] - qx, ry = cb[nb*3+1] - qy, rz = cb[nb*3+2] - qz;
        float dist = sqrtf(rx*rx + ry*ry + rz*rz);
        float inv  = 1.0f / (dist + 1e-6f);
        float nx = rx*inv, ny = ry*inv, nz = rz*inv;
        float* gm = sATF + t * 10;
        gm[0] = dist; gm[1] = rx; gm[2] = ry; gm[3] = rz;
        gm[4] = atan2f(ny, nx); gm[5] = atan2f(nz, nx); gm[6] = atan2f(nz, ny);
        gm[7] = nx; gm[8] = ny; gm[9] = nz;
    }
    __syncthreads();

    // ---- stage 1 (fp32): geom[128][10] @ W1[10][64] -> bufF stride 64 ----
    {
        int j = t & 63, r0 = (t >> 6) * 16;
        float acc[16];
        float bj = b1[j];
#pragma unroll
        for (int r = 0; r < 16; r++) acc[r] = bj;
#pragma unroll
        for (int k = 0; k < 10; k++) {
            float wv = W1[k*64 + j];
#pragma unroll
            for (int r = 0; r < 16; r++)
                acc[r] = fmaf(wv, sATF[(r0 + r)*10 + k], acc[r]);
        }
#pragma unroll
        for (int r = 0; r < 16; r++) bufF[(r0 + r)*64 + j] = acc[r];
    }
    __syncthreads();
    ln_rows_s<64, true, 16>(bufF, 64, ENC_R, g1, be1);
    __syncthreads();

    // cvt h1 -> A-fragments (K=64 -> KT=8, MT=8)
    cvt_to_afrag<8, 8>(bufF, 64, sATF, t, 512);
    __syncthreads();

    // ---- stage 2 (mma): h1[128x64] @ W2[64x128] -> bufF stride 136 ----
    {
        const int mtg = w & 3;           // mtiles {2mtg, 2mtg+1}
        const int npg = w >> 2;          // ntps {2npg, 2npg+1} -> ntiles 4
        float acc[2][4][4];
#pragma unroll
        for (int a = 0; a < 2; a++)
#pragma unroll
            for (int c = 0; c < 4; c++)
#pragma unroll
                for (int k = 0; k < 4; k++) acc[a][c][k] = 0.f;
        const uint4* AT = (const uint4*)sATF;
        const uint4* BT = (const uint4*)g_W2f;
#pragma unroll
        for (int kt = 0; kt < 8; kt++) {
            uint4 a0 = AT[(kt*8 + 2*mtg    )*32 + lane];
            uint4 a1 = AT[(kt*8 + 2*mtg + 1)*32 + lane];
            uint4 bq0 = BT[(kt*8 + 2*npg    )*32 + lane];
            uint4 bq1 = BT[(kt*8 + 2*npg + 1)*32 + lane];
            mma_tf32(acc[0][0], a0, bq0.x, bq0.y);
            mma_tf32(acc[0][1], a0, bq0.z, bq0.w);
            mma_tf32(acc[0][2], a0, bq1.x, bq1.y);
            mma_tf32(acc[0][3], a0, bq1.z, bq1.w);
            mma_tf32(acc[1][0], a1, bq0.x, bq0.y);
            mma_tf32(acc[1][1], a1, bq0.z, bq0.w);
            mma_tf32(acc[1][2], a1, bq1.x, bq1.y);
            mma_tf32(acc[1][3], a1, bq1.z, bq1.w);
        }
#pragma unroll
        for (int a = 0; a < 2; a++) {
            int row = (2*mtg + a)*16 + g;
#pragma unroll
            for (int c = 0; c < 4; c++) {
                int col = (4*npg + c)*8 + 2*tg;
                float2 bb = *(const float2*)&b2[col];
                *(float2*)&bufF[ row     *136 + col] =
                    make_float2(acc[a][c][0] + bb.x, acc[a][c][1] + bb.y);
                *(float2*)&bufF[(row + 8)*136 + col] =
                    make_float2(acc[a][c][2] + bb.x, acc[a][c][3] + bb.y);
            }
        }
    }
    __syncthreads();
    ln_rows_s<128, true, 16>(bufF, 136, ENC_R, g2, be2);
    __syncthreads();

    // cvt h2 -> A-fragments (K=128 -> KT=16, MT=8)
    cvt_to_afrag<16, 8>(bufF, 136, sATF, t, 512);
    __syncthreads();

    // ---- stage 3 (mma): h2[128x128] @ W3[128x256] -> bufF stride 260 ----
    // warp: mtiles {2mtg, 2mtg+1}, ntiles [8*nq, 8*nq+8) in two passes of 2 ntps
    {
        const int mtg = w & 3;
        const int nq  = w >> 2;
        const uint4* AT = (const uint4*)sATF;
        const uint4* BT = (const uint4*)g_W3f;
#pragma unroll
        for (int p = 0; p < 2; p++) {
            const int np0 = 4*nq + 2*p;      // ntps {np0, np0+1}
            float acc[2][4][4];
#pragma unroll
            for (int a = 0; a < 2; a++)
#pragma unroll
                for (int c = 0; c < 4; c++)
#pragma unroll
                    for (int k = 0; k < 4; k++) acc[a][c][k] = 0.f;
#pragma unroll
            for (int kt = 0; kt < 16; kt++) {
                uint4 a0 = AT[(kt*8 + 2*mtg    )*32 + lane];
                uint4 a1 = AT[(kt*8 + 2*mtg + 1)*32 + lane];
                uint4 bq0 = BT[(kt*16 + np0    )*32 + lane];
                uint4 bq1 = BT[(kt*16 + np0 + 1)*32 + lane];
                mma_tf32(acc[0][0], a0, bq0.x, bq0.y);
                mma_tf32(acc[0][1], a0, bq0.z, bq0.w);
                mma_tf32(acc[0][2], a0, bq1.x, bq1.y);
                mma_tf32(acc[0][3], a0, bq1.z, bq1.w);
                mma_tf32(acc[1][0], a1, bq0.x, bq0.y);
                mma_tf32(acc[1][1], a1, bq0.z, bq0.w);
                mma_tf32(acc[1][2], a1, bq1.x, bq1.y);
                mma_tf32(acc[1][3], a1, bq1.z, bq1.w);
            }
#pragma unroll
            for (int a = 0; a < 2; a++) {
                int row = (2*mtg + a)*16 + g;
#pragma unroll
                for (int c = 0; c < 4; c++) {
                    int col = (2*np0 + c)*8 + 2*tg;
                    float2 bb = *(const float2*)&b3[col];
                    *(float2*)&bufF[ row     *260 + col] =
                        make_float2(acc[a][c][0] + bb.x, acc[a][c][1] + bb.y);
                    *(float2*)&bufF[(row + 8)*260 + col] =
                        make_float2(acc[a][c][2] + bb.x, acc[a][c][3] + bb.y);
                }
            }
        }
    }
    __syncthreads();
    ln_rows_s<256, false, 16>(bufF, 260, ENC_R, g3, be3);
    __syncthreads();

    // mean over K=16 neighbor rows per query
    for (int idx = t; idx < ENC_G * 256; idx += 512) {
        int gq = idx >> 8, j = idx & 255;
        float s = 0.f;
#pragma unroll
        for (int r = 0; r < 16; r++) s += bufF[(gq*16 + r)*260 + j];
        g_agg[(size_t)(q0 + gq)*256 + j] = s * (1.0f/16.0f);
    }
}

// ---------------------------------------------------------------------------
// Kernel 3: aggregator via tf32 mma (proven R8 configuration, 89us).
// ---------------------------------------------------------------------------
#define AGG_RB 64
#define AGG_SMEM_FLOATS (16384 + 16640)

__global__ __launch_bounds__(512, 1) void agg_kernel(
    const float* __restrict__ ba1,
    const float* __restrict__ ga1, const float* __restrict__ bea1,
    const float* __restrict__ ba2,
    float* __restrict__ out)
{
    extern __shared__ float sm[];
    float* sATF = sm;            // 16384: A fragments (KT=32, MT=4)
    float* bufF = sm + 16384;    // 16640
    const int t = threadIdx.x;
    const int w = t >> 5;
    const int lane = t & 31;
    const int g = lane >> 2, tg = lane & 3;
    const size_t row0 = (size_t)blockIdx.x * AGG_RB;

    {
        float4* dst = (float4*)bufF;
        const float4* src = (const float4*)(g_agg + row0*256);
        for (int i = t; i < AGG_RB*256/4; i += 512) dst[i] = src[i];
    }
    __syncthreads();
    cvt_to_afrag<32, 4>(bufF, 256, sATF, t, 512);
    __syncthreads();

    const int mt2 = w & 1;
    const int ng  = w >> 1;

    {   // stage A: in @ Wa1 + ba1 -> bufF stride 260
        float acc[2][4][4];
#pragma unroll
        for (int a = 0; a < 2; a++)
#pragma unroll
            for (int c = 0; c < 4; c++)
#pragma unroll
                for (int k = 0; k < 4; k++) acc[a][c][k] = 0.f;
        const uint4* AT = (const uint4*)sATF;
        const uint4* BT = (const uint4*)g_Wa1f;
#pragma unroll 8
        for (int kt = 0; kt < 32; kt++) {
            uint4 a0 = AT[(kt*4 + mt2*2    )*32 + lane];
            uint4 a1 = AT[(kt*4 + mt2*2 + 1)*32 + lane];
            uint4 bq0 = BT[(kt*16 + 2*ng    )*32 + lane];
            uint4 bq1 = BT[(kt*16 + 2*ng + 1)*32 + lane];
            mma_tf32(acc[0][0], a0, bq0.x, bq0.y);
            mma_tf32(acc[0][1], a0, bq0.z, bq0.w);
            mma_tf32(acc[0][2], a0, bq1.x, bq1.y);
            mma_tf32(acc[0][3], a0, bq1.z, bq1.w);
            mma_tf32(acc[1][0], a1, bq0.x, bq0.y);
            mma_tf32(acc[1][1], a1, bq0.z, bq0.w);
            mma_tf32(acc[1][2], a1, bq1.x, bq1.y);
            mma_tf32(acc[1][3], a1, bq1.z, bq1.w);
        }
#pragma unroll
        for (int a = 0; a < 2; a++) {
            int row = (mt2*2 + a)*16 + g;
#pragma unroll
            for (int c = 0; c < 4; c++) {
                int col = (4*ng + c)*8 + 2*tg;
                float2 bb = *(const float2*)&ba1[col];
                *(float2*)&bufF[ row     *260 + col] =
                    make_float2(acc[a][c][0] + bb.x, acc[a][c][1] + bb.y);
                *(float2*)&bufF[(row + 8)*260 + col] =
                    make_float2(acc[a][c][2] + bb.x, acc[a][c][3] + bb.y);
            }
        }
    }
    __syncthreads();
    ln_rows_s<256, true, 16>(bufF, 260, AGG_RB, ga1, bea1);
    __syncthreads();
    cvt_to_afrag<32, 4>(bufF, 260, sATF, t, 512);
    __syncthreads();

    {   // stage B: mid @ Wa2 + ba2 -> out
        float acc[2][4][4];
#pragma unroll
        for (int a = 0; a < 2; a++)
#pragma unroll
            for (int c = 0; c < 4; c++)
#pragma unroll
                for (int k = 0; k < 4; k++) acc[a][c][k] = 0.f;
        const uint4* AT = (const uint4*)sATF;
        const uint4* BT = (const uint4*)g_Wa2f;
#pragma unroll 8
        for (int kt = 0; kt < 32; kt++) {
            uint4 a0 = AT[(kt*4 + mt2*2    )*32 + lane];
            uint4 a1 = AT[(kt*4 + mt2*2 + 1)*32 + lane];
            uint4 bq0 = BT[(kt*16 + 2*ng    )*32 + lane];
            uint4 bq1 = BT[(kt*16 + 2*ng + 1)*32 + lane];
            mma_tf32(acc[0][0], a0, bq0.x, bq0.y);
            mma_tf32(acc[0][1], a0, bq0.z, bq0.w);
            mma_tf32(acc[0][2], a0, bq1.x, bq1.y);
            mma_tf32(acc[0][3], a0, bq1.z, bq1.w);
            mma_tf32(acc[1][0], a1, bq0.x, bq0.y);
            mma_tf32(acc[1][1], a1, bq0.z, bq0.w);
            mma_tf32(acc[1][2], a1, bq1.x, bq1.y);
            mma_tf32(acc[1][3], a1, bq1.z, bq1.w);
        }
#pragma unroll
        for (int a = 0; a < 2; a++) {
            size_t row = row0 + (mt2*2 + a)*16 + g;
#pragma unroll
            for (int c = 0; c < 4; c++) {
                int col = (4*ng + c)*8 + 2*tg;
                float2 bb = *(const float2*)&ba2[col];
                *(float2*)&out[ row     *256 + col] =
                    make_float2(acc[a][c][0] + bb.x, acc[a][c][1] + bb.y);
                *(float2*)&out[(row + 8)*256 + col] =
                    make_float2(acc[a][c][2] + bb.x, acc[a][c][3] + bb.y);
            }
        }
    }
}

// ---------------------------------------------------------------------------
extern "C" void kernel_launch(void* const* d_in, const int* in_sizes, int n_in,
                              void* d_out, int out_size)
{
    const float* coords = (const float*)d_in[0];
    const float* W1  = (const float*)d_in[1];
    const float* b1  = (const float*)d_in[2];
    const float* g1  = (const float*)d_in[3];
    const float* be1 = (const float*)d_in[4];
    const float* W2  = (const float*)d_in[5];
    const float* b2  = (const float*)d_in[6];
    const float* g2  = (const float*)d_in[7];
    const float* be2 = (const float*)d_in[8];
    const float* W3  = (const float*)d_in[9];
    const float* b3  = (const float*)d_in[10];
    const float* g3  = (const float*)d_in[11];
    const float* be3 = (const float*)d_in[12];
    const float* Wa1 = (const float*)d_in[13];
    const float* ba1 = (const float*)d_in[14];
    const float* ga1 = (const float*)d_in[15];
    const float* bea1= (const float*)d_in[16];
    const float* Wa2 = (const float*)d_in[17];
    const float* ba2 = (const float*)d_in[18];
    float* out = (float*)d_out;

    cudaFuncSetAttribute(encoder_kernel,
                         cudaFuncAttributeMaxDynamicSharedMemorySize,
                         ENC_SMEM_FLOATS * (int)sizeof(float));
    cudaFuncSetAttribute(agg_kernel,
                         cudaFuncAttributeMaxDynamicSharedMemorySize,
                         AGG_SMEM_FLOATS * (int)sizeof(float));

    prep_kernel<<<(43008 + 255)/256, 256>>>(W2, W3, Wa1, Wa2);

    knn_kernel<<<B_ * (N_ / 128), 256>>>(coords);

    encoder_kernel<<<M_ / ENC_G, 512, ENC_SMEM_FLOATS * sizeof(float)>>>(
        coords, W1, b1, g1, be1, b2, g2, be2, b3, g3, be3);

    agg_kernel<<<M_ / AGG_RB, 512, AGG_SMEM_FLOATS * sizeof(float)>>>(
        ba1, ga1, bea1, ba2, out);
}